// round 10
// baseline (speedup 1.0000x reference)
#include <cuda_runtime.h>
#include <math.h>
#include <stdint.h>

#define NSRC   2048
#define NGRID  50000
#define NLOCS  500
#define KTOP   5
#define NSLICE 512
#define SL     98           // ceil(50000/512); slice 510 has 20, slice 511 empty
#define NPAIR  49           // SL/2
#define SPT    4            // sources per thread in slice_min
#define SMT    128          // threads in slice_min
#define FINF   __int_as_float(0x7f800000)
#define IBIG   0x7fffffff

// ---------------- device scratch ----------------
__device__ float g_sd[NSRC * NSLICE];      // per (src, slice) min "e"
__device__ int   g_topk[NSRC * KTOP];      // final top-5 grid idx per src

// ---------------- f32x2 packed helpers (sm_103a FFMA2) ----------------
__device__ __forceinline__ unsigned long long pk2(float lo, float hi) {
    unsigned long long r;
    asm("mov.b64 %0, {%1, %2};"
        : "=l"(r) : "r"(__float_as_uint(lo)), "r"(__float_as_uint(hi)));
    return r;
}
__device__ __forceinline__ unsigned long long fma2(unsigned long long a,
                                                   unsigned long long b,
                                                   unsigned long long c) {
    unsigned long long d;
    asm("fma.rn.f32x2 %0, %1, %2, %3;" : "=l"(d) : "l"(a), "l"(b), "l"(c));
    return d;
}
__device__ __forceinline__ void upk2(unsigned long long v, float& lo, float& hi) {
    unsigned int a, b;
    asm("mov.b64 {%0, %1}, %2;" : "=r"(a), "=r"(b) : "l"(v));
    lo = __uint_as_float(a);
    hi = __uint_as_float(b);
}
__device__ __forceinline__ float fsqrt_approx(float x) {
    float r;
    asm("sqrt.approx.f32 %0, %1;" : "=f"(r) : "f"(x));
    return r;
}

// ============ kernel 1: per-(src, slice) branchless minimum ============
// grid = (4, 512); 128 threads; SPT=4 sources per thread; 2048 blocks for
// ~86% occupancy. Compile-time 49-pair inner loop (short/empty slices are
// padded to +inf e). Grid points processed in packed pairs with
// fma.rn.f32x2 (per-lane IEEE fma, bit-identical to select's fmaf).
// Ordering key: e = |g|^2 - 2*s.g  (== d2 - |s|^2, same order as ref d2).
__global__ __launch_bounds__(SMT)
void slice_min_kernel(const float* __restrict__ src,
                      const float* __restrict__ grid) {
    __shared__ float4 tileA[NPAIR];   // (x0, x1, y0, y1)
    __shared__ float4 tileB[NPAIR];   // (z0, z1, w0, w1)

    const int slice = blockIdx.y;
    const int base  = slice * SL;
    const int n     = min(SL, NGRID - base);      // 98, 20, or <=0 (empty)

    const int s0 = blockIdx.x * (SMT * SPT) + threadIdx.x;

    if (n <= 0) {      // empty tail slice: min = +inf
#pragma unroll
        for (int k = 0; k < SPT; k++)
            g_sd[(s0 + k * SMT) * NSLICE + slice] = FINF;
        return;
    }

    if (threadIdx.x < NPAIR) {
        const int p  = threadIdx.x;
        const int j0 = 2 * p;
        const int j1 = j0 + 1;
        // pad coords 1e30 -> w = inf -> e = +inf (no NaN in fma chain)
        float x0 = 1e30f, y0 = 1e30f, z0 = 1e30f, w0;
        float x1 = 1e30f, y1 = 1e30f, z1 = 1e30f, w1;
        if (j0 < n) {
            const int g0 = base + j0;
            x0 = grid[g0 * 3 + 0] / 1000.0f;
            y0 = grid[g0 * 3 + 1] / 1000.0f;
            z0 = grid[g0 * 3 + 2] / 1000.0f;
        }
        if (j1 < n) {
            const int g1 = base + j1;
            x1 = grid[g1 * 3 + 0] / 1000.0f;
            y1 = grid[g1 * 3 + 1] / 1000.0f;
            z1 = grid[g1 * 3 + 2] / 1000.0f;
        }
        w0 = __fadd_rn(__fadd_rn(__fmul_rn(x0, x0), __fmul_rn(y0, y0)),
                       __fmul_rn(z0, z0));
        w1 = __fadd_rn(__fadd_rn(__fmul_rn(x1, x1), __fmul_rn(y1, y1)),
                       __fmul_rn(z1, z1));
        tileA[p] = make_float4(x0, x1, y0, y1);
        tileB[p] = make_float4(z0, z1, w0, w1);
    }
    __syncthreads();

    unsigned long long mx2[SPT], my2[SPT], mz2[SPT];
#pragma unroll
    for (int k = 0; k < SPT; k++) {
        const int s = s0 + k * SMT;
        float mx = -2.0f * (src[s * 3 + 0] / 1000.0f);
        float my = -2.0f * (src[s * 3 + 1] / 1000.0f);
        float mz = -2.0f * (src[s * 3 + 2] / 1000.0f);
        mx2[k] = pk2(mx, mx);
        my2[k] = pk2(my, my);
        mz2[k] = pk2(mz, mz);
    }

    float accL[SPT], accH[SPT];
#pragma unroll
    for (int k = 0; k < SPT; k++) { accL[k] = FINF; accH[k] = FINF; }

#pragma unroll 7
    for (int p = 0; p < NPAIR; p++) {
        float4 A = tileA[p];
        float4 B = tileB[p];
        unsigned long long xx = pk2(A.x, A.y);
        unsigned long long yy = pk2(A.z, A.w);
        unsigned long long zz = pk2(B.x, B.y);
        unsigned long long ww = pk2(B.z, B.w);
#pragma unroll
        for (int k = 0; k < SPT; k++) {
            unsigned long long e = fma2(mz2[k], zz, ww);
            e = fma2(my2[k], yy, e);
            e = fma2(mx2[k], xx, e);
            float lo, hi;
            upk2(e, lo, hi);
            accL[k] = fminf(accL[k], lo);
            accH[k] = fminf(accH[k], hi);
        }
    }

#pragma unroll
    for (int k = 0; k < SPT; k++) {
        const int s = s0 + k * SMT;
        g_sd[s * NSLICE + slice] = fminf(accL[k], accH[k]);
    }
}

// ============ kernel 2: exact top-5 per source ============
// block = one source, 256 threads.
//  A) 5 rounds of block-argmin over 512 slice minima (2 per thread)
//     -> 5 candidate slices (provably contain the global top-5).
//  B) recompute e for the <=490 candidate points into smem (batched loads).
//  C) 5 rounds of block-argmin with grid-index tie-break -> g_topk.
__global__ __launch_bounds__(256)
void select_kernel(const float* __restrict__ src,
                   const float* __restrict__ grid) {
    const int s = blockIdx.x;
    const int t = threadIdx.x;
    const int lane = t & 31;
    const int wid  = t >> 5;

    __shared__ float sv[NSLICE];
    __shared__ int   csl[KTOP];
    __shared__ float ev[KTOP * SL];
    __shared__ int   eg[KTOP * SL];
    __shared__ float wv[8];
    __shared__ int   wj[8];
    __shared__ int   win_g;

    sv[t]       = g_sd[s * NSLICE + t];
    sv[t + 256] = g_sd[s * NSLICE + t + 256];
    __syncthreads();

    // ---- stage A: 5 smallest slice minima (tie -> lower slice id) ----
    for (int r = 0; r < KTOP; r++) {
        float v  = sv[t];
        int   j  = t;
        float v1 = sv[t + 256];
        if (v1 < v) { v = v1; j = t + 256; }    // distinct ids, strict ok
#pragma unroll
        for (int off = 16; off > 0; off >>= 1) {
            float ov = __shfl_xor_sync(0xffffffffu, v, off);
            int   oj = __shfl_xor_sync(0xffffffffu, j, off);
            if (ov < v || (ov == v && oj < j)) { v = ov; j = oj; }
        }
        if (lane == 0) { wv[wid] = v; wj[wid] = j; }
        __syncthreads();
        if (t < 8) {
            float v2 = wv[t];
            int   j2 = wj[t];
#pragma unroll
            for (int off = 4; off > 0; off >>= 1) {
                float ov = __shfl_xor_sync(0x000000ffu, v2, off);
                int   oj = __shfl_xor_sync(0x000000ffu, j2, off);
                if (ov < v2 || (ov == v2 && oj < j2)) { v2 = ov; j2 = oj; }
            }
            if (t == 0) { csl[r] = j2; sv[j2] = FINF; }
        }
        __syncthreads();
    }

    // ---- stage B: candidate e values (490 tasks, batched loads) ----
    const float mx = -2.0f * (src[s * 3 + 0] / 1000.0f);
    const float my = -2.0f * (src[s * 3 + 1] / 1000.0f);
    const float mz = -2.0f * (src[s * 3 + 2] / 1000.0f);

    const int TOT = KTOP * SL;    // 490
    for (int p = t; p < TOT; p += 256) {
        const int k = p / SL;
        const int j = p - k * SL;
        const int gi = csl[k] * SL + j;
        float e = FINF;
        int   gidx = IBIG;
        if (gi < NGRID) {
            float x = grid[gi * 3 + 0] / 1000.0f;
            float y = grid[gi * 3 + 1] / 1000.0f;
            float z = grid[gi * 3 + 2] / 1000.0f;
            float n2 = __fadd_rn(__fadd_rn(__fmul_rn(x, x), __fmul_rn(y, y)),
                                 __fmul_rn(z, z));
            e = fmaf(mx, x, fmaf(my, y, fmaf(mz, z, n2)));
            gidx = gi;
        }
        ev[p] = e;
        eg[p] = gidx;
    }
    __syncthreads();

    // ---- stage C: 5 rounds argmin over 490 (tie -> lower grid idx) ----
    for (int r = 0; r < KTOP; r++) {
        float bv = FINF;
        int   bg = IBIG;
        for (int p = t; p < TOT; p += 256) {
            float v = ev[p];
            int   g = eg[p];
            if (v < bv || (v == bv && g < bg)) { bv = v; bg = g; }
        }
#pragma unroll
        for (int off = 16; off > 0; off >>= 1) {
            float ov = __shfl_xor_sync(0xffffffffu, bv, off);
            int   og = __shfl_xor_sync(0xffffffffu, bg, off);
            if (ov < bv || (ov == bv && og < bg)) { bv = ov; bg = og; }
        }
        if (lane == 0) { wv[wid] = bv; wj[wid] = bg; }
        __syncthreads();
        if (t < 8) {
            float v2 = wv[t];
            int   g2 = wj[t];
#pragma unroll
            for (int off = 4; off > 0; off >>= 1) {
                float ov = __shfl_xor_sync(0x000000ffu, v2, off);
                int   og = __shfl_xor_sync(0x000000ffu, g2, off);
                if (ov < v2 || (ov == v2 && og < g2)) { v2 = ov; g2 = og; }
            }
            if (t == 0) { g_topk[s * KTOP + r] = g2; win_g = g2; }
        }
        __syncthreads();
        for (int p = t; p < TOT; p += 256)
            if (eg[p] == win_g) ev[p] = FINF;   // grid idx unique
        __syncthreads();
    }
}

// ============ kernel 3: fused tail — 4 sources per block ============
// 512 blocks x 512 threads.
//  stage 1: 2000 (source, station) bias-mean tasks; consecutive tids map to
//           consecutive stations -> coalesced 8B-stride row streams.
//  stage 2: each thread emits 4 outputs (one per source) at station t.
__global__ __launch_bounds__(512)
void tail_kernel(const float* __restrict__ src,
                 const int*   __restrict__ ind,
                 const float* __restrict__ log_amp,
                 const int*   __restrict__ phase,
                 const float* __restrict__ locs,
                 const float* __restrict__ mag_coef,
                 const float* __restrict__ eps_coef,
                 const float* __restrict__ dep_coef,
                 const float* __restrict__ bias,
                 float*       __restrict__ out) {
    const int s0  = blockIdx.x * 4;
    const int tid = threadIdx.x;

    __shared__ float bsum[4][NLOCS];
    __shared__ int   tks[4 * KTOP];

    if (tid < 4 * KTOP) tks[tid] = g_topk[s0 * KTOP + tid];
    __syncthreads();

    const int ph = phase[0];

    // ---- stage 1: bias means for 4 sources ----
    for (int task = tid; task < 4 * NLOCS; task += 512) {
        const int ss = task / NLOCS;
        const int j  = task - ss * NLOCS;
        const int col = j * 2 + ph;
        float acc = __ldg(&bias[(size_t)tks[ss * KTOP + 0] * (NLOCS * 2) + col]);
        acc += __ldg(&bias[(size_t)tks[ss * KTOP + 1] * (NLOCS * 2) + col]);
        acc += __ldg(&bias[(size_t)tks[ss * KTOP + 2] * (NLOCS * 2) + col]);
        acc += __ldg(&bias[(size_t)tks[ss * KTOP + 3] * (NLOCS * 2) + col]);
        acc += __ldg(&bias[(size_t)tks[ss * KTOP + 4] * (NLOCS * 2) + col]);
        bsum[ss][j] = acc / 5.0f;
    }
    __syncthreads();

    // ---- stage 2: epilogue, 4 outputs per thread ----
    if (tid >= NLOCS) return;

    const float ec    = eps_coef[ph];
    const float dc    = dep_coef[ph];
    const float denom = fmaxf(mag_coef[ph], 1e-12f);

    const int li = ind[tid];
    const float lx = locs[li * 3 + 0];
    const float ly = locs[li * 3 + 1];
    const float lz = locs[li * 3 + 2];

#pragma unroll
    for (int ss = 0; ss < 4; ss++) {
        const int s = s0 + ss;
        const float sx = src[s * 3 + 0];
        const float sy = src[s * 3 + 1];
        const float sz = src[s * 3 + 2];

        const float dx = sx - lx;
        const float dy = sy - ly;
        const float d0  = fsqrt_approx(__fadd_rn(__fmul_rn(dx, dx),
                                                 __fmul_rn(dy, dy)));
        const float ld0 = __log10f(d0 + 1.0f);
        const float ldd = __log10f(fabsf(sz - lz) + 1.0f);

        const float b  = bsum[ss][li];
        const float la = log_amp[s * NLOCS + tid];
        out[s * NLOCS + tid] = (la - ec * ld0 - dc * ldd - b) / denom;
    }
}

// ---------------- launch ----------------
extern "C" void kernel_launch(void* const* d_in, const int* in_sizes, int n_in,
                              void* d_out, int out_size) {
    const float* src      = (const float*)d_in[0];
    const int*   ind      = (const int*)  d_in[1];
    const float* log_amp  = (const float*)d_in[2];
    const int*   phase    = (const int*)  d_in[3];
    const float* locs     = (const float*)d_in[4];
    const float* grid     = (const float*)d_in[5];
    const float* mag_coef = (const float*)d_in[6];
    const float* eps_coef = (const float*)d_in[7];
    const float* dep_coef = (const float*)d_in[8];
    const float* bias     = (const float*)d_in[9];
    float* out = (float*)d_out;

    dim3 g1(NSRC / (SMT * SPT), NSLICE);
    slice_min_kernel<<<g1, SMT>>>(src, grid);

    select_kernel<<<NSRC, 256>>>(src, grid);

    tail_kernel<<<NSRC / 4, 512>>>(src, ind, log_amp, phase, locs,
                                   mag_coef, eps_coef, dep_coef, bias, out);
}

// round 11
// speedup vs baseline: 1.1502x; 1.1502x over previous
#include <cuda_runtime.h>
#include <math.h>
#include <stdint.h>

#define NSRC   2048
#define NGRID  50000
#define NLOCS  500
#define KTOP   5
#define NSLICE 256
#define SL     196          // ceil(50000/256); last slice has 20 points
#define NPAIR  98           // SL/2
#define SPT    4            // sources per thread in slice_min
#define SMT    128          // threads in slice_min
#define FINF   __int_as_float(0x7f800000)
#define IBIG   0x7fffffff

// ---------------- device scratch ----------------
__device__ float g_sd[NSRC * NSLICE];      // per (src, slice) min "e"

// ---------------- f32x2 packed helpers (sm_103a FFMA2) ----------------
__device__ __forceinline__ unsigned long long pk2(float lo, float hi) {
    unsigned long long r;
    asm("mov.b64 %0, {%1, %2};"
        : "=l"(r) : "r"(__float_as_uint(lo)), "r"(__float_as_uint(hi)));
    return r;
}
__device__ __forceinline__ unsigned long long fma2(unsigned long long a,
                                                   unsigned long long b,
                                                   unsigned long long c) {
    unsigned long long d;
    asm("fma.rn.f32x2 %0, %1, %2, %3;" : "=l"(d) : "l"(a), "l"(b), "l"(c));
    return d;
}
__device__ __forceinline__ void upk2(unsigned long long v, float& lo, float& hi) {
    unsigned int a, b;
    asm("mov.b64 {%0, %1}, %2;" : "=r"(a), "=r"(b) : "l"(v));
    lo = __uint_as_float(a);
    hi = __uint_as_float(b);
}
__device__ __forceinline__ float fsqrt_approx(float x) {
    float r;
    asm("sqrt.approx.f32 %0, %1;" : "=f"(r) : "f"(x));
    return r;
}

// ============ kernel 1: per-(src, slice) branchless minimum ============
// (exact R8-measured version: 19.7 us) grid = (4, 256); 128 threads;
// SPT=4 sources per thread; packed pairs with fma.rn.f32x2 (per-lane IEEE
// fma, bit-identical to the select stage's fmaf).
// Ordering key: e = |g|^2 - 2*s.g  (== d2 - |s|^2, same order as ref d2).
__global__ __launch_bounds__(SMT)
void slice_min_kernel(const float* __restrict__ src,
                      const float* __restrict__ grid) {
    __shared__ float4 tileA[NPAIR];   // (x0, x1, y0, y1)
    __shared__ float4 tileB[NPAIR];   // (z0, z1, w0, w1)

    const int slice = blockIdx.y;
    const int base  = slice * SL;
    const int n     = min(SL, NGRID - base);      // 196 or 20
    const int npair = (n + 1) >> 1;

    if (threadIdx.x < npair) {
        const int p  = threadIdx.x;
        const int g0 = base + 2 * p;
        const int g1 = g0 + 1;
        float x0 = grid[g0 * 3 + 0] / 1000.0f;
        float y0 = grid[g0 * 3 + 1] / 1000.0f;
        float z0 = grid[g0 * 3 + 2] / 1000.0f;
        float w0 = __fadd_rn(__fadd_rn(__fmul_rn(x0, x0), __fmul_rn(y0, y0)),
                             __fmul_rn(z0, z0));
        float x1 = 1e30f, y1 = 1e30f, z1 = 1e30f, w1 = 1e30f;  // pad -> huge e
        if (2 * p + 1 < n) {
            x1 = grid[g1 * 3 + 0] / 1000.0f;
            y1 = grid[g1 * 3 + 1] / 1000.0f;
            z1 = grid[g1 * 3 + 2] / 1000.0f;
            w1 = __fadd_rn(__fadd_rn(__fmul_rn(x1, x1), __fmul_rn(y1, y1)),
                           __fmul_rn(z1, z1));
        }
        tileA[p] = make_float4(x0, x1, y0, y1);
        tileB[p] = make_float4(z0, z1, w0, w1);
    }
    __syncthreads();

    const int s0 = blockIdx.x * (SMT * SPT) + threadIdx.x;

    unsigned long long mx2[SPT], my2[SPT], mz2[SPT];
#pragma unroll
    for (int k = 0; k < SPT; k++) {
        const int s = s0 + k * SMT;
        float mx = -2.0f * (src[s * 3 + 0] / 1000.0f);
        float my = -2.0f * (src[s * 3 + 1] / 1000.0f);
        float mz = -2.0f * (src[s * 3 + 2] / 1000.0f);
        mx2[k] = pk2(mx, mx);
        my2[k] = pk2(my, my);
        mz2[k] = pk2(mz, mz);
    }

    float accL[SPT], accH[SPT];
#pragma unroll
    for (int k = 0; k < SPT; k++) { accL[k] = FINF; accH[k] = FINF; }

#pragma unroll 2
    for (int p = 0; p < npair; p++) {
        float4 A = tileA[p];
        float4 B = tileB[p];
        unsigned long long xx = pk2(A.x, A.y);
        unsigned long long yy = pk2(A.z, A.w);
        unsigned long long zz = pk2(B.x, B.y);
        unsigned long long ww = pk2(B.z, B.w);
#pragma unroll
        for (int k = 0; k < SPT; k++) {
            unsigned long long e = fma2(mz2[k], zz, ww);
            e = fma2(my2[k], yy, e);
            e = fma2(mx2[k], xx, e);
            float lo, hi;
            upk2(e, lo, hi);
            accL[k] = fminf(accL[k], lo);
            accH[k] = fminf(accH[k], hi);
        }
    }

#pragma unroll
    for (int k = 0; k < SPT; k++) {
        const int s = s0 + k * SMT;
        g_sd[s * NSLICE + slice] = fminf(accL[k], accH[k]);
    }
}

// ============ kernel 2: fused select + bias mean + epilogue ============
// 2048 blocks x 512 threads; block = one source. All stages block-wide.
//  A) 5 rounds of block-argmin over 256 slice minima -> 5 candidate slices
//     (provably contain the global top-5; lex tie-break on slice id).
//  B) recompute e for the <=980 candidate points into smem (batched, MLP~6).
//  C) 5 rounds of block-argmin with grid-index tie-break -> tks[5].
//  D) bias means: thread j streams 5 rows coalesced (float2) -> bsum[500].
//  E) epilogue: one output per thread.
__global__ __launch_bounds__(512)
void tail_kernel(const float* __restrict__ src,
                 const int*   __restrict__ ind,
                 const float* __restrict__ log_amp,
                 const int*   __restrict__ phase,
                 const float* __restrict__ locs,
                 const float* __restrict__ mag_coef,
                 const float* __restrict__ eps_coef,
                 const float* __restrict__ dep_coef,
                 const float* __restrict__ bias,
                 const float* __restrict__ grid,
                 float*       __restrict__ out) {
    const int s    = blockIdx.x;
    const int t    = threadIdx.x;
    const int lane = t & 31;
    const int wid  = t >> 5;

    __shared__ float sv[NSLICE];
    __shared__ int   csl[KTOP];
    __shared__ int   tks[KTOP];
    __shared__ float ev[KTOP * SL];
    __shared__ int   eg[KTOP * SL];
    __shared__ float wv[16];
    __shared__ int   wj[16];
    __shared__ int   win_g;
    __shared__ float bsum[NLOCS];

    if (t < NSLICE) sv[t] = g_sd[s * NSLICE + t];
    __syncthreads();

    // ---- stage A: 5 smallest slice minima (tie -> lower slice id) ----
    for (int r = 0; r < KTOP; r++) {
        float v = (t < NSLICE) ? sv[t] : FINF;
        int   j = (t < NSLICE) ? t : IBIG;
#pragma unroll
        for (int off = 16; off > 0; off >>= 1) {
            float ov = __shfl_xor_sync(0xffffffffu, v, off);
            int   oj = __shfl_xor_sync(0xffffffffu, j, off);
            if (ov < v || (ov == v && oj < j)) { v = ov; j = oj; }
        }
        if (lane == 0) { wv[wid] = v; wj[wid] = j; }
        __syncthreads();
        if (t < 16) {
            float v2 = wv[t];
            int   j2 = wj[t];
#pragma unroll
            for (int off = 8; off > 0; off >>= 1) {
                float ov = __shfl_xor_sync(0x0000ffffu, v2, off);
                int   oj = __shfl_xor_sync(0x0000ffffu, j2, off);
                if (ov < v2 || (ov == v2 && oj < j2)) { v2 = ov; j2 = oj; }
            }
            if (t == 0) { csl[r] = j2; sv[j2] = FINF; }
        }
        __syncthreads();
    }

    // ---- stage B: candidate e values (980 tasks, batched loads) ----
    const float mx = -2.0f * (src[s * 3 + 0] / 1000.0f);
    const float my = -2.0f * (src[s * 3 + 1] / 1000.0f);
    const float mz = -2.0f * (src[s * 3 + 2] / 1000.0f);

    const int TOT = KTOP * SL;    // 980
    for (int p = t; p < TOT; p += 512) {
        const int k = p / SL;
        const int j = p - k * SL;
        const int gi = csl[k] * SL + j;
        float e = FINF;
        int   gidx = IBIG;
        if (gi < NGRID) {
            float x = grid[gi * 3 + 0] / 1000.0f;
            float y = grid[gi * 3 + 1] / 1000.0f;
            float z = grid[gi * 3 + 2] / 1000.0f;
            float n2 = __fadd_rn(__fadd_rn(__fmul_rn(x, x), __fmul_rn(y, y)),
                                 __fmul_rn(z, z));
            e = fmaf(mx, x, fmaf(my, y, fmaf(mz, z, n2)));
            gidx = gi;
        }
        ev[p] = e;
        eg[p] = gidx;
    }
    __syncthreads();

    // ---- stage C: 5 rounds argmin over 980 (tie -> lower grid idx) ----
    for (int r = 0; r < KTOP; r++) {
        float bv = FINF;
        int   bg = IBIG;
        for (int p = t; p < TOT; p += 512) {
            float v = ev[p];
            int   g = eg[p];
            if (v < bv || (v == bv && g < bg)) { bv = v; bg = g; }
        }
#pragma unroll
        for (int off = 16; off > 0; off >>= 1) {
            float ov = __shfl_xor_sync(0xffffffffu, bv, off);
            int   og = __shfl_xor_sync(0xffffffffu, bg, off);
            if (ov < bv || (ov == bv && og < bg)) { bv = ov; bg = og; }
        }
        if (lane == 0) { wv[wid] = bv; wj[wid] = bg; }
        __syncthreads();
        if (t < 16) {
            float v2 = wv[t];
            int   g2 = wj[t];
#pragma unroll
            for (int off = 8; off > 0; off >>= 1) {
                float ov = __shfl_xor_sync(0x0000ffffu, v2, off);
                int   og = __shfl_xor_sync(0x0000ffffu, g2, off);
                if (ov < v2 || (ov == v2 && og < g2)) { v2 = ov; g2 = og; }
            }
            if (t == 0) { tks[r] = g2; win_g = g2; }
        }
        __syncthreads();
        for (int p = t; p < TOT; p += 512)
            if (eg[p] == win_g) ev[p] = FINF;   // valid grid ids unique
        __syncthreads();
    }

    const int ph = phase[0];

    // ---- stage D: bias means (coalesced float2 row streams, MLP=5) ----
    if (t < NLOCS) {
        const int t0 = tks[0], t1 = tks[1], t2 = tks[2],
                  t3 = tks[3], t4 = tks[4];
        float2 v0 = __ldg((const float2*)(bias + (size_t)t0 * (NLOCS * 2)) + t);
        float2 v1 = __ldg((const float2*)(bias + (size_t)t1 * (NLOCS * 2)) + t);
        float2 v2 = __ldg((const float2*)(bias + (size_t)t2 * (NLOCS * 2)) + t);
        float2 v3 = __ldg((const float2*)(bias + (size_t)t3 * (NLOCS * 2)) + t);
        float2 v4 = __ldg((const float2*)(bias + (size_t)t4 * (NLOCS * 2)) + t);
        float acc = (ph ? v0.y : v0.x) + (ph ? v1.y : v1.x) +
                    (ph ? v2.y : v2.x) + (ph ? v3.y : v3.x) +
                    (ph ? v4.y : v4.x);
        bsum[t] = acc / 5.0f;
    }
    __syncthreads();

    // ---- stage E: epilogue ----
    if (t >= NLOCS) return;

    const float ec    = eps_coef[ph];
    const float dc    = dep_coef[ph];
    const float denom = fmaxf(mag_coef[ph], 1e-12f);

    const float sx = src[s * 3 + 0];
    const float sy = src[s * 3 + 1];
    const float sz = src[s * 3 + 2];

    const int li = ind[t];
    const float lx = locs[li * 3 + 0];
    const float ly = locs[li * 3 + 1];
    const float lz = locs[li * 3 + 2];

    const float dx = sx - lx;
    const float dy = sy - ly;
    const float d0  = fsqrt_approx(__fadd_rn(__fmul_rn(dx, dx),
                                             __fmul_rn(dy, dy)));
    const float ld0 = __log10f(d0 + 1.0f);
    const float ldd = __log10f(fabsf(sz - lz) + 1.0f);

    const float b  = bsum[li];
    const float la = log_amp[s * NLOCS + t];
    out[s * NLOCS + t] = (la - ec * ld0 - dc * ldd - b) / denom;
}

// ---------------- launch ----------------
extern "C" void kernel_launch(void* const* d_in, const int* in_sizes, int n_in,
                              void* d_out, int out_size) {
    const float* src      = (const float*)d_in[0];
    const int*   ind      = (const int*)  d_in[1];
    const float* log_amp  = (const float*)d_in[2];
    const int*   phase    = (const int*)  d_in[3];
    const float* locs     = (const float*)d_in[4];
    const float* grid     = (const float*)d_in[5];
    const float* mag_coef = (const float*)d_in[6];
    const float* eps_coef = (const float*)d_in[7];
    const float* dep_coef = (const float*)d_in[8];
    const float* bias     = (const float*)d_in[9];
    float* out = (float*)d_out;

    dim3 g1(NSRC / (SMT * SPT), NSLICE);
    slice_min_kernel<<<g1, SMT>>>(src, grid);

    tail_kernel<<<NSRC, 512>>>(src, ind, log_amp, phase, locs,
                               mag_coef, eps_coef, dep_coef, bias,
                               grid, out);
}

// round 12
// speedup vs baseline: 1.4566x; 1.2665x over previous
#include <cuda_runtime.h>
#include <math.h>
#include <stdint.h>

#define NSRC   2048
#define NGRID  50000
#define NLOCS  500
#define KTOP   5
#define NSLICE 256
#define SL     196          // ceil(50000/256); last slice has 20 points
#define NPAIR  98           // SL/2
#define SPT    2            // sources per thread in slice_min
#define SMT    128          // threads in slice_min
#define FINF   __int_as_float(0x7f800000)
#define IBIG   0x7fffffff

// ---------------- device scratch ----------------
__device__ float g_sd[NSRC * NSLICE];      // per (src, slice) min "e"
__device__ int   g_topk[NSRC * KTOP];      // final top-5 grid idx per src

// ---------------- f32x2 packed helpers (sm_103a FFMA2) ----------------
__device__ __forceinline__ unsigned long long pk2(float lo, float hi) {
    unsigned long long r;
    asm("mov.b64 %0, {%1, %2};"
        : "=l"(r) : "r"(__float_as_uint(lo)), "r"(__float_as_uint(hi)));
    return r;
}
__device__ __forceinline__ unsigned long long fma2(unsigned long long a,
                                                   unsigned long long b,
                                                   unsigned long long c) {
    unsigned long long d;
    asm("fma.rn.f32x2 %0, %1, %2, %3;" : "=l"(d) : "l"(a), "l"(b), "l"(c));
    return d;
}
__device__ __forceinline__ void upk2(unsigned long long v, float& lo, float& hi) {
    unsigned int a, b;
    asm("mov.b64 {%0, %1}, %2;" : "=r"(a), "=r"(b) : "l"(v));
    lo = __uint_as_float(a);
    hi = __uint_as_float(b);
}
__device__ __forceinline__ float fsqrt_approx(float x) {
    float r;
    asm("sqrt.approx.f32 %0, %1;" : "=f"(r) : "f"(x));
    return r;
}

// ============ kernel 1: per-(src, slice) branchless minimum ============
// grid = (NSRC/(SMT*SPT), NSLICE) = (8, 256) = 2048 blocks; 128 threads;
// SPT=2 sources per thread -> 8192 warps total (occupancy cap ~86% vs 43%
// at SPT=4). Packed pairs with fma.rn.f32x2 (per-lane IEEE fma,
// bit-identical to select's fmaf).
// Ordering key: e = |g|^2 - 2*s.g  (== d2 - |s|^2, same order as ref d2).
__global__ __launch_bounds__(SMT)
void slice_min_kernel(const float* __restrict__ src,
                      const float* __restrict__ grid) {
    __shared__ float4 tileA[NPAIR];   // (x0, x1, y0, y1)
    __shared__ float4 tileB[NPAIR];   // (z0, z1, w0, w1)

    const int slice = blockIdx.y;
    const int base  = slice * SL;
    const int n     = min(SL, NGRID - base);      // 196 or 20
    const int npair = (n + 1) >> 1;

    if (threadIdx.x < npair) {
        const int p  = threadIdx.x;
        const int g0 = base + 2 * p;
        const int g1 = g0 + 1;
        float x0 = grid[g0 * 3 + 0] / 1000.0f;
        float y0 = grid[g0 * 3 + 1] / 1000.0f;
        float z0 = grid[g0 * 3 + 2] / 1000.0f;
        float w0 = __fadd_rn(__fadd_rn(__fmul_rn(x0, x0), __fmul_rn(y0, y0)),
                             __fmul_rn(z0, z0));
        float x1 = 1e30f, y1 = 1e30f, z1 = 1e30f, w1 = 1e30f;  // pad -> huge e
        if (2 * p + 1 < n) {
            x1 = grid[g1 * 3 + 0] / 1000.0f;
            y1 = grid[g1 * 3 + 1] / 1000.0f;
            z1 = grid[g1 * 3 + 2] / 1000.0f;
            w1 = __fadd_rn(__fadd_rn(__fmul_rn(x1, x1), __fmul_rn(y1, y1)),
                           __fmul_rn(z1, z1));
        }
        tileA[p] = make_float4(x0, x1, y0, y1);
        tileB[p] = make_float4(z0, z1, w0, w1);
    }
    __syncthreads();

    const int s0 = blockIdx.x * (SMT * SPT) + threadIdx.x;

    unsigned long long mx2[SPT], my2[SPT], mz2[SPT];
#pragma unroll
    for (int k = 0; k < SPT; k++) {
        const int s = s0 + k * SMT;
        float mx = -2.0f * (src[s * 3 + 0] / 1000.0f);
        float my = -2.0f * (src[s * 3 + 1] / 1000.0f);
        float mz = -2.0f * (src[s * 3 + 2] / 1000.0f);
        mx2[k] = pk2(mx, mx);
        my2[k] = pk2(my, my);
        mz2[k] = pk2(mz, mz);
    }

    float accL[SPT], accH[SPT];
#pragma unroll
    for (int k = 0; k < SPT; k++) { accL[k] = FINF; accH[k] = FINF; }

#pragma unroll 4
    for (int p = 0; p < npair; p++) {
        float4 A = tileA[p];
        float4 B = tileB[p];
        unsigned long long xx = pk2(A.x, A.y);
        unsigned long long yy = pk2(A.z, A.w);
        unsigned long long zz = pk2(B.x, B.y);
        unsigned long long ww = pk2(B.z, B.w);
#pragma unroll
        for (int k = 0; k < SPT; k++) {
            unsigned long long e = fma2(mz2[k], zz, ww);
            e = fma2(my2[k], yy, e);
            e = fma2(mx2[k], xx, e);
            float lo, hi;
            upk2(e, lo, hi);
            accL[k] = fminf(accL[k], lo);
            accH[k] = fminf(accH[k], hi);
        }
    }

#pragma unroll
    for (int k = 0; k < SPT; k++) {
        const int s = s0 + k * SMT;
        g_sd[s * NSLICE + slice] = fminf(accL[k], accH[k]);
    }
}

// ============ kernel 2: exact top-5 per source ============
// block = one source, 256 threads. (proven R8 version)
//  A) 5 rounds of block-argmin over 256 slice minima -> 5 candidate slices
//     (provably contain the global top-5).
//  B) recompute e for the <=980 candidate points into smem.
//  C) 5 rounds of block-argmin with grid-index tie-break -> g_topk.
__global__ __launch_bounds__(256)
void select_kernel(const float* __restrict__ src,
                   const float* __restrict__ grid) {
    const int s = blockIdx.x;
    const int t = threadIdx.x;
    const int lane = t & 31;
    const int wid  = t >> 5;

    __shared__ float sv[NSLICE];
    __shared__ int   csl[KTOP];
    __shared__ float ev[KTOP * SL];
    __shared__ int   eg[KTOP * SL];
    __shared__ float wv[8];
    __shared__ int   wj[8];
    __shared__ int   win_g;

    sv[t] = g_sd[s * NSLICE + t];
    __syncthreads();

    // ---- stage A: 5 smallest slice minima (tie -> lower slice id) ----
    for (int r = 0; r < KTOP; r++) {
        float v = sv[t];
        int   j = t;
#pragma unroll
        for (int off = 16; off > 0; off >>= 1) {
            float ov = __shfl_xor_sync(0xffffffffu, v, off);
            int   oj = __shfl_xor_sync(0xffffffffu, j, off);
            if (ov < v || (ov == v && oj < j)) { v = ov; j = oj; }
        }
        if (lane == 0) { wv[wid] = v; wj[wid] = j; }
        __syncthreads();
        if (t < 8) {
            float v2 = wv[t];
            int   j2 = wj[t];
#pragma unroll
            for (int off = 4; off > 0; off >>= 1) {
                float ov = __shfl_xor_sync(0x000000ffu, v2, off);
                int   oj = __shfl_xor_sync(0x000000ffu, j2, off);
                if (ov < v2 || (ov == v2 && oj < j2)) { v2 = ov; j2 = oj; }
            }
            if (t == 0) { csl[r] = j2; sv[j2] = FINF; }
        }
        __syncthreads();
    }

    // ---- stage B: candidate e values ----
    const float mx = -2.0f * (src[s * 3 + 0] / 1000.0f);
    const float my = -2.0f * (src[s * 3 + 1] / 1000.0f);
    const float mz = -2.0f * (src[s * 3 + 2] / 1000.0f);

    if (t < SL) {
#pragma unroll
        for (int k = 0; k < KTOP; k++) {
            int gi = csl[k] * SL + t;
            float e = FINF;
            if (gi < NGRID) {
                float x = grid[gi * 3 + 0] / 1000.0f;
                float y = grid[gi * 3 + 1] / 1000.0f;
                float z = grid[gi * 3 + 2] / 1000.0f;
                float n2 = __fadd_rn(__fadd_rn(__fmul_rn(x, x),
                                               __fmul_rn(y, y)),
                                     __fmul_rn(z, z));
                e = fmaf(mx, x, fmaf(my, y, fmaf(mz, z, n2)));
            }
            ev[k * SL + t] = e;
            eg[k * SL + t] = gi;
        }
    }
    __syncthreads();

    // ---- stage C: 5 rounds argmin over 980 (tie -> lower grid idx) ----
    const int TOT = KTOP * SL;
    for (int r = 0; r < KTOP; r++) {
        float bv = FINF;
        int   bg = IBIG;
        for (int p = t; p < TOT; p += 256) {
            float v = ev[p];
            int   g = eg[p];
            if (v < bv || (v == bv && g < bg)) { bv = v; bg = g; }
        }
#pragma unroll
        for (int off = 16; off > 0; off >>= 1) {
            float ov = __shfl_xor_sync(0xffffffffu, bv, off);
            int   og = __shfl_xor_sync(0xffffffffu, bg, off);
            if (ov < bv || (ov == bv && og < bg)) { bv = ov; bg = og; }
        }
        if (lane == 0) { wv[wid] = bv; wj[wid] = bg; }
        __syncthreads();
        if (t < 8) {
            float v2 = wv[t];
            int   g2 = wj[t];
#pragma unroll
            for (int off = 4; off > 0; off >>= 1) {
                float ov = __shfl_xor_sync(0x000000ffu, v2, off);
                int   og = __shfl_xor_sync(0x000000ffu, g2, off);
                if (ov < v2 || (ov == v2 && og < g2)) { v2 = ov; g2 = og; }
            }
            if (t == 0) { g_topk[s * KTOP + r] = g2; win_g = g2; }
        }
        __syncthreads();
        for (int p = t; p < TOT; p += 256)
            if (eg[p] == win_g) ev[p] = FINF;   // grid idx unique across slices
        __syncthreads();
    }
}

// ============ kernel 3: fused tail — 4 sources per block ============
// (proven R8 version) 512 blocks x 512 threads.
__global__ __launch_bounds__(512)
void tail_kernel(const float* __restrict__ src,
                 const int*   __restrict__ ind,
                 const float* __restrict__ log_amp,
                 const int*   __restrict__ phase,
                 const float* __restrict__ locs,
                 const float* __restrict__ mag_coef,
                 const float* __restrict__ eps_coef,
                 const float* __restrict__ dep_coef,
                 const float* __restrict__ bias,
                 float*       __restrict__ out) {
    const int s0  = blockIdx.x * 4;
    const int tid = threadIdx.x;

    __shared__ float bsum[4][NLOCS];
    __shared__ int   tks[4 * KTOP];

    if (tid < 4 * KTOP) tks[tid] = g_topk[s0 * KTOP + tid];
    __syncthreads();

    const int ph = phase[0];

    // ---- stage 1: bias means for 4 sources ----
    for (int task = tid; task < 4 * NLOCS; task += 512) {
        const int ss = task / NLOCS;
        const int j  = task - ss * NLOCS;
        const int col = j * 2 + ph;
        float acc = __ldg(&bias[(size_t)tks[ss * KTOP + 0] * (NLOCS * 2) + col]);
        acc += __ldg(&bias[(size_t)tks[ss * KTOP + 1] * (NLOCS * 2) + col]);
        acc += __ldg(&bias[(size_t)tks[ss * KTOP + 2] * (NLOCS * 2) + col]);
        acc += __ldg(&bias[(size_t)tks[ss * KTOP + 3] * (NLOCS * 2) + col]);
        acc += __ldg(&bias[(size_t)tks[ss * KTOP + 4] * (NLOCS * 2) + col]);
        bsum[ss][j] = acc / 5.0f;
    }
    __syncthreads();

    // ---- stage 2: epilogue, 4 outputs per thread ----
    if (tid >= NLOCS) return;

    const float ec    = eps_coef[ph];
    const float dc    = dep_coef[ph];
    const float denom = fmaxf(mag_coef[ph], 1e-12f);

    const int li = ind[tid];
    const float lx = locs[li * 3 + 0];
    const float ly = locs[li * 3 + 1];
    const float lz = locs[li * 3 + 2];

#pragma unroll
    for (int ss = 0; ss < 4; ss++) {
        const int s = s0 + ss;
        const float sx = src[s * 3 + 0];
        const float sy = src[s * 3 + 1];
        const float sz = src[s * 3 + 2];

        const float dx = sx - lx;
        const float dy = sy - ly;
        const float d0  = fsqrt_approx(__fadd_rn(__fmul_rn(dx, dx),
                                                 __fmul_rn(dy, dy)));
        const float ld0 = __log10f(d0 + 1.0f);
        const float ldd = __log10f(fabsf(sz - lz) + 1.0f);

        const float b  = bsum[ss][li];
        const float la = log_amp[s * NLOCS + tid];
        out[s * NLOCS + tid] = (la - ec * ld0 - dc * ldd - b) / denom;
    }
}

// ---------------- launch ----------------
extern "C" void kernel_launch(void* const* d_in, const int* in_sizes, int n_in,
                              void* d_out, int out_size) {
    const float* src      = (const float*)d_in[0];
    const int*   ind      = (const int*)  d_in[1];
    const float* log_amp  = (const float*)d_in[2];
    const int*   phase    = (const int*)  d_in[3];
    const float* locs     = (const float*)d_in[4];
    const float* grid     = (const float*)d_in[5];
    const float* mag_coef = (const float*)d_in[6];
    const float* eps_coef = (const float*)d_in[7];
    const float* dep_coef = (const float*)d_in[8];
    const float* bias     = (const float*)d_in[9];
    float* out = (float*)d_out;

    dim3 g1(NSRC / (SMT * SPT), NSLICE);
    slice_min_kernel<<<g1, SMT>>>(src, grid);

    select_kernel<<<NSRC, 256>>>(src, grid);

    tail_kernel<<<NSRC / 4, 512>>>(src, ind, log_amp, phase, locs,
                                   mag_coef, eps_coef, dep_coef, bias, out);
}

// round 14
// speedup vs baseline: 1.6845x; 1.1564x over previous
#include <cuda_runtime.h>
#include <math.h>
#include <stdint.h>

#define NSRC   2048
#define NGRID  50000
#define NLOCS  500
#define KTOP   5
#define NSLICE 256
#define SL     196          // ceil(50000/256); last slice has 20 points
#define NPAIR  98           // SL/2
#define SPT    4            // sources per thread in slice_min
#define SMT    128          // threads in slice_min
#define FINF   __int_as_float(0x7f800000)
#define IBIG   0x7fffffff

// ---------------- device scratch ----------------
__device__ float g_sd[NSRC * NSLICE];      // per (src, slice) min "e"
__device__ int   g_topk[NSRC * KTOP];      // final top-5 grid idx per src

// ---------------- f32x2 packed helpers (sm_103a FFMA2) ----------------
__device__ __forceinline__ unsigned long long pk2(float lo, float hi) {
    unsigned long long r;
    asm("mov.b64 %0, {%1, %2};"
        : "=l"(r) : "r"(__float_as_uint(lo)), "r"(__float_as_uint(hi)));
    return r;
}
__device__ __forceinline__ unsigned long long fma2(unsigned long long a,
                                                   unsigned long long b,
                                                   unsigned long long c) {
    unsigned long long d;
    asm("fma.rn.f32x2 %0, %1, %2, %3;" : "=l"(d) : "l"(a), "l"(b), "l"(c));
    return d;
}
__device__ __forceinline__ void upk2(unsigned long long v, float& lo, float& hi) {
    unsigned int a, b;
    asm("mov.b64 {%0, %1}, %2;" : "=r"(a), "=r"(b) : "l"(v));
    lo = __uint_as_float(a);
    hi = __uint_as_float(b);
}
__device__ __forceinline__ float fsqrt_approx(float x) {
    float r;
    asm("sqrt.approx.f32 %0, %1;" : "=f"(r) : "f"(x));
    return r;
}

// lexicographic (value, index): lower value wins; tie -> lower index
__device__ __forceinline__ bool lexless(float a, int ai, float b, int bi) {
    return (a < b) || (a == b && ai < bi);
}

// ============ kernel 1: per-(src, slice) branchless minimum ============
// (R8-exact, measured 19.7 us) grid = (4, 256); 128 threads; SPT=4.
// Packed pairs with fma.rn.f32x2 (per-lane IEEE fma, bit-identical to
// select's fmaf chain -> slice minima match the rescan exactly).
// Ordering key: e = |g|^2 - 2*s.g  (== d2 - |s|^2, same order as ref d2).
__global__ __launch_bounds__(SMT)
void slice_min_kernel(const float* __restrict__ src,
                      const float* __restrict__ grid) {
    __shared__ float4 tileA[NPAIR];   // (x0, x1, y0, y1)
    __shared__ float4 tileB[NPAIR];   // (z0, z1, w0, w1)

    const int slice = blockIdx.y;
    const int base  = slice * SL;
    const int n     = min(SL, NGRID - base);      // 196 or 20
    const int npair = (n + 1) >> 1;

    if (threadIdx.x < npair) {
        const int p  = threadIdx.x;
        const int g0 = base + 2 * p;
        const int g1 = g0 + 1;
        float x0 = grid[g0 * 3 + 0] / 1000.0f;
        float y0 = grid[g0 * 3 + 1] / 1000.0f;
        float z0 = grid[g0 * 3 + 2] / 1000.0f;
        float w0 = __fadd_rn(__fadd_rn(__fmul_rn(x0, x0), __fmul_rn(y0, y0)),
                             __fmul_rn(z0, z0));
        float x1 = 1e30f, y1 = 1e30f, z1 = 1e30f, w1 = 1e30f;  // pad -> huge e
        if (2 * p + 1 < n) {
            x1 = grid[g1 * 3 + 0] / 1000.0f;
            y1 = grid[g1 * 3 + 1] / 1000.0f;
            z1 = grid[g1 * 3 + 2] / 1000.0f;
            w1 = __fadd_rn(__fadd_rn(__fmul_rn(x1, x1), __fmul_rn(y1, y1)),
                           __fmul_rn(z1, z1));
        }
        tileA[p] = make_float4(x0, x1, y0, y1);
        tileB[p] = make_float4(z0, z1, w0, w1);
    }
    __syncthreads();

    const int s0 = blockIdx.x * (SMT * SPT) + threadIdx.x;

    unsigned long long mx2[SPT], my2[SPT], mz2[SPT];
#pragma unroll
    for (int k = 0; k < SPT; k++) {
        const int s = s0 + k * SMT;
        float mx = -2.0f * (src[s * 3 + 0] / 1000.0f);
        float my = -2.0f * (src[s * 3 + 1] / 1000.0f);
        float mz = -2.0f * (src[s * 3 + 2] / 1000.0f);
        mx2[k] = pk2(mx, mx);
        my2[k] = pk2(my, my);
        mz2[k] = pk2(mz, mz);
    }

    float accL[SPT], accH[SPT];
#pragma unroll
    for (int k = 0; k < SPT; k++) { accL[k] = FINF; accH[k] = FINF; }

#pragma unroll 2
    for (int p = 0; p < npair; p++) {
        float4 A = tileA[p];
        float4 B = tileB[p];
        unsigned long long xx = pk2(A.x, A.y);
        unsigned long long yy = pk2(A.z, A.w);
        unsigned long long zz = pk2(B.x, B.y);
        unsigned long long ww = pk2(B.z, B.w);
#pragma unroll
        for (int k = 0; k < SPT; k++) {
            unsigned long long e = fma2(mz2[k], zz, ww);
            e = fma2(my2[k], yy, e);
            e = fma2(mx2[k], xx, e);
            float lo, hi;
            upk2(e, lo, hi);
            accL[k] = fminf(accL[k], lo);
            accH[k] = fminf(accH[k], hi);
        }
    }

#pragma unroll
    for (int k = 0; k < SPT; k++) {
        const int s = s0 + k * SMT;
        g_sd[s * NSLICE + slice] = fminf(accL[k], accH[k]);
    }
}

// ============ kernel 2: exact top-5 per source (3 barriers) ============
// block = one source, 256 threads.
//  A) warp w: 5 shuffle-argmin rounds over its 32 slice minima -> sorted
//     5-list; warp 0 merges 8 lists -> 5 candidate slices (lex tie-break;
//     provably contain the global top-5 since slice minima bit-match the
//     rescan values).
//  B/C) each thread computes e for <=4 of the 980 candidate points from
//     GMEM (batched), branchless lane sort-4 by (e, gidx), 5 warp-merge
//     rounds -> sorted 5-list per warp; warp 0 merges 8 lists -> g_topk.
__global__ __launch_bounds__(256)
void select_kernel(const float* __restrict__ src,
                   const float* __restrict__ grid) {
    const int s    = blockIdx.x;
    const int t    = threadIdx.x;
    const int lane = t & 31;
    const int wid  = t >> 5;

    __shared__ float swv[8 * KTOP];
    __shared__ int   swj[8 * KTOP];
    __shared__ int   csl[KTOP];

    // ---- stage A: per-warp top-5 of slice minima ----
    {
        float v = g_sd[s * NSLICE + t];
        int   j = t;
#pragma unroll
        for (int r = 0; r < KTOP; r++) {
            float bv = v; int bi = j;
#pragma unroll
            for (int off = 16; off > 0; off >>= 1) {
                float ov = __shfl_xor_sync(0xffffffffu, bv, off);
                int   oi = __shfl_xor_sync(0xffffffffu, bi, off);
                if (lexless(ov, oi, bv, bi)) { bv = ov; bi = oi; }
            }
            if (lane == 0) { swv[wid * KTOP + r] = bv; swj[wid * KTOP + r] = bi; }
            if (v == bv && j == bi) { v = FINF; j = IBIG; }  // ids unique
        }
    }
    __syncthreads();

    // ---- warp 0: merge 8 sorted 5-lists -> csl ----
    if (wid == 0) {
        float h0 = FINF, h1 = FINF, h2 = FINF, h3 = FINF, h4 = FINF;
        int   g0 = IBIG, g1 = IBIG, g2 = IBIG, g3 = IBIG, g4 = IBIG;
        if (lane < 8) {
            h0 = swv[lane * KTOP + 0]; g0 = swj[lane * KTOP + 0];
            h1 = swv[lane * KTOP + 1]; g1 = swj[lane * KTOP + 1];
            h2 = swv[lane * KTOP + 2]; g2 = swj[lane * KTOP + 2];
            h3 = swv[lane * KTOP + 3]; g3 = swj[lane * KTOP + 3];
            h4 = swv[lane * KTOP + 4]; g4 = swj[lane * KTOP + 4];
        }
#pragma unroll
        for (int r = 0; r < KTOP; r++) {
            float bv = h0; int bi = g0;
#pragma unroll
            for (int off = 16; off > 0; off >>= 1) {
                float ov = __shfl_xor_sync(0xffffffffu, bv, off);
                int   oi = __shfl_xor_sync(0xffffffffu, bi, off);
                if (lexless(ov, oi, bv, bi)) { bv = ov; bi = oi; }
            }
            if (lane == 0) csl[r] = bi;
            if (h0 == bv && g0 == bi) {
                h0 = h1; g0 = g1; h1 = h2; g1 = g2;
                h2 = h3; g2 = g3; h3 = h4; g3 = g4;
                h4 = FINF; g4 = IBIG;
            }
        }
    }
    __syncthreads();

    // ---- stage B/C: rescan <=980 candidates, lane sort-4, warp merge ----
    const float mx = -2.0f * (src[s * 3 + 0] / 1000.0f);
    const float my = -2.0f * (src[s * 3 + 1] / 1000.0f);
    const float mz = -2.0f * (src[s * 3 + 2] / 1000.0f);

    float cv[4];
    int   cg[4];
#pragma unroll
    for (int i = 0; i < 4; i++) {
        const int p = t + 256 * i;
        float e = FINF;
        int   gidx = IBIG;
        if (p < KTOP * SL) {
            const int k  = p / SL;
            const int jj = p - k * SL;
            const int gi = csl[k] * SL + jj;
            if (gi < NGRID) {
                float x = grid[gi * 3 + 0] / 1000.0f;
                float y = grid[gi * 3 + 1] / 1000.0f;
                float z = grid[gi * 3 + 2] / 1000.0f;
                float n2 = __fadd_rn(__fadd_rn(__fmul_rn(x, x),
                                               __fmul_rn(y, y)),
                                     __fmul_rn(z, z));
                e = fmaf(mx, x, fmaf(my, y, fmaf(mz, z, n2)));
                gidx = gi;
            }
        }
        cv[i] = e;
        cg[i] = gidx;
    }

    // branchless sort-4 ascending by (e, gidx)
#define CE(a, b) { bool sw = lexless(cv[b], cg[b], cv[a], cg[a]);            \
                   float tv = sw ? cv[b] : cv[a]; float uv = sw ? cv[a] : cv[b]; \
                   int   tg = sw ? cg[b] : cg[a]; int   ug = sw ? cg[a] : cg[b]; \
                   cv[a] = tv; cv[b] = uv; cg[a] = tg; cg[b] = ug; }
    CE(0, 1) CE(2, 3) CE(0, 2) CE(1, 3) CE(1, 2)
#undef CE

    // warp merge: top-5 over 32 sorted 4-lists
#pragma unroll
    for (int r = 0; r < KTOP; r++) {
        float bv = cv[0]; int bi = cg[0];
#pragma unroll
        for (int off = 16; off > 0; off >>= 1) {
            float ov = __shfl_xor_sync(0xffffffffu, bv, off);
            int   oi = __shfl_xor_sync(0xffffffffu, bi, off);
            if (lexless(ov, oi, bv, bi)) { bv = ov; bi = oi; }
        }
        if (lane == 0) { swv[wid * KTOP + r] = bv; swj[wid * KTOP + r] = bi; }
        if (cv[0] == bv && cg[0] == bi) {   // real ids unique; INF pads benign
            cv[0] = cv[1]; cg[0] = cg[1]; cv[1] = cv[2]; cg[1] = cg[2];
            cv[2] = cv[3]; cg[2] = cg[3]; cv[3] = FINF; cg[3] = IBIG;
        }
    }
    __syncthreads();

    // ---- warp 0: merge 8 sorted 5-lists -> g_topk ----
    if (wid == 0) {
        float h0 = FINF, h1 = FINF, h2 = FINF, h3 = FINF, h4 = FINF;
        int   g0 = IBIG, g1 = IBIG, g2 = IBIG, g3 = IBIG, g4 = IBIG;
        if (lane < 8) {
            h0 = swv[lane * KTOP + 0]; g0 = swj[lane * KTOP + 0];
            h1 = swv[lane * KTOP + 1]; g1 = swj[lane * KTOP + 1];
            h2 = swv[lane * KTOP + 2]; g2 = swj[lane * KTOP + 2];
            h3 = swv[lane * KTOP + 3]; g3 = swj[lane * KTOP + 3];
            h4 = swv[lane * KTOP + 4]; g4 = swj[lane * KTOP + 4];
        }
#pragma unroll
        for (int r = 0; r < KTOP; r++) {
            float bv = h0; int bi = g0;
#pragma unroll
            for (int off = 16; off > 0; off >>= 1) {
                float ov = __shfl_xor_sync(0xffffffffu, bv, off);
                int   oi = __shfl_xor_sync(0xffffffffu, bi, off);
                if (lexless(ov, oi, bv, bi)) { bv = ov; bi = oi; }
            }
            if (lane == 0) g_topk[s * KTOP + r] = bi;
            if (h0 == bv && g0 == bi) {
                h0 = h1; g0 = g1; h1 = h2; g1 = g2;
                h2 = h3; g2 = g3; h3 = h4; g3 = g4;
                h4 = FINF; g4 = IBIG;
            }
        }
    }
}

// ============ kernel 3: fused tail — 4 sources per block ============
// (R8-exact) 512 blocks x 512 threads.
__global__ __launch_bounds__(512)
void tail_kernel(const float* __restrict__ src,
                 const int*   __restrict__ ind,
                 const float* __restrict__ log_amp,
                 const int*   __restrict__ phase,
                 const float* __restrict__ locs,
                 const float* __restrict__ mag_coef,
                 const float* __restrict__ eps_coef,
                 const float* __restrict__ dep_coef,
                 const float* __restrict__ bias,
                 float*       __restrict__ out) {
    const int s0  = blockIdx.x * 4;
    const int tid = threadIdx.x;

    __shared__ float bsum[4][NLOCS];
    __shared__ int   tks[4 * KTOP];

    if (tid < 4 * KTOP) tks[tid] = g_topk[s0 * KTOP + tid];
    __syncthreads();

    const int ph = phase[0];

    // ---- stage 1: bias means for 4 sources ----
    for (int task = tid; task < 4 * NLOCS; task += 512) {
        const int ss = task / NLOCS;
        const int j  = task - ss * NLOCS;
        const int col = j * 2 + ph;
        float acc = __ldg(&bias[(size_t)tks[ss * KTOP + 0] * (NLOCS * 2) + col]);
        acc += __ldg(&bias[(size_t)tks[ss * KTOP + 1] * (NLOCS * 2) + col]);
        acc += __ldg(&bias[(size_t)tks[ss * KTOP + 2] * (NLOCS * 2) + col]);
        acc += __ldg(&bias[(size_t)tks[ss * KTOP + 3] * (NLOCS * 2) + col]);
        acc += __ldg(&bias[(size_t)tks[ss * KTOP + 4] * (NLOCS * 2) + col]);
        bsum[ss][j] = acc / 5.0f;
    }
    __syncthreads();

    // ---- stage 2: epilogue, 4 outputs per thread ----
    if (tid >= NLOCS) return;

    const float ec    = eps_coef[ph];
    const float dc    = dep_coef[ph];
    const float denom = fmaxf(mag_coef[ph], 1e-12f);

    const int li = ind[tid];
    const float lx = locs[li * 3 + 0];
    const float ly = locs[li * 3 + 1];
    const float lz = locs[li * 3 + 2];

#pragma unroll
    for (int ss = 0; ss < 4; ss++) {
        const int s = s0 + ss;
        const float sx = src[s * 3 + 0];
        const float sy = src[s * 3 + 1];
        const float sz = src[s * 3 + 2];

        const float dx = sx - lx;
        const float dy = sy - ly;
        const float d0  = fsqrt_approx(__fadd_rn(__fmul_rn(dx, dx),
                                                 __fmul_rn(dy, dy)));
        const float ld0 = __log10f(d0 + 1.0f);
        const float ldd = __log10f(fabsf(sz - lz) + 1.0f);

        const float b  = bsum[ss][li];
        const float la = log_amp[s * NLOCS + tid];
        out[s * NLOCS + tid] = (la - ec * ld0 - dc * ldd - b) / denom;
    }
}

// ---------------- launch ----------------
extern "C" void kernel_launch(void* const* d_in, const int* in_sizes, int n_in,
                              void* d_out, int out_size) {
    const float* src      = (const float*)d_in[0];
    const int*   ind      = (const int*)  d_in[1];
    const float* log_amp  = (const float*)d_in[2];
    const int*   phase    = (const int*)  d_in[3];
    const float* locs     = (const float*)d_in[4];
    const float* grid     = (const float*)d_in[5];
    const float* mag_coef = (const float*)d_in[6];
    const float* eps_coef = (const float*)d_in[7];
    const float* dep_coef = (const float*)d_in[8];
    const float* bias     = (const float*)d_in[9];
    float* out = (float*)d_out;

    dim3 g1(NSRC / (SMT * SPT), NSLICE);
    slice_min_kernel<<<g1, SMT>>>(src, grid);

    select_kernel<<<NSRC, 256>>>(src, grid);

    tail_kernel<<<NSRC / 4, 512>>>(src, ind, log_amp, phase, locs,
                                   mag_coef, eps_coef, dep_coef, bias, out);
}

// round 15
// speedup vs baseline: 1.6947x; 1.0061x over previous
#include <cuda_runtime.h>
#include <math.h>
#include <stdint.h>

#define NSRC   2048
#define NGRID  50000
#define NLOCS  500
#define KTOP   5
#define NSLICE 256
#define SL     196          // ceil(50000/256); last slice has 20 points
#define NPAIR  98           // SL/2
#define SPT    4            // sources per thread in slice_min
#define SMT    128          // threads in slice_min
#define FINF   __int_as_float(0x7f800000)
#define IBIG   0x7fffffff

// ---------------- device scratch ----------------
__device__ float g_sd[NSRC * NSLICE];      // per (src, slice) min "e"
__device__ int   g_topk[NSRC * KTOP];      // final top-5 grid idx per src

// ---------------- f32x2 packed helpers (sm_103a FFMA2) ----------------
__device__ __forceinline__ unsigned long long pk2(float lo, float hi) {
    unsigned long long r;
    asm("mov.b64 %0, {%1, %2};"
        : "=l"(r) : "r"(__float_as_uint(lo)), "r"(__float_as_uint(hi)));
    return r;
}
__device__ __forceinline__ unsigned long long fma2(unsigned long long a,
                                                   unsigned long long b,
                                                   unsigned long long c) {
    unsigned long long d;
    asm("fma.rn.f32x2 %0, %1, %2, %3;" : "=l"(d) : "l"(a), "l"(b), "l"(c));
    return d;
}
__device__ __forceinline__ void upk2(unsigned long long v, float& lo, float& hi) {
    unsigned int a, b;
    asm("mov.b64 {%0, %1}, %2;" : "=r"(a), "=r"(b) : "l"(v));
    lo = __uint_as_float(a);
    hi = __uint_as_float(b);
}
__device__ __forceinline__ float fsqrt_approx(float x) {
    float r;
    asm("sqrt.approx.f32 %0, %1;" : "=f"(r) : "f"(x));
    return r;
}

// lexicographic (value, index): lower value wins; tie -> lower index
__device__ __forceinline__ bool lexless(float a, int ai, float b, int bi) {
    return (a < b) || (a == b && ai < bi);
}

// ============ kernel 1: per-(src, slice) branchless minimum ============
// grid = (4, 256); 128 threads; SPT=4. Tile stored PRE-PACKED as
// ulonglong2 so LDS.128 lands each f32x2 operand in an aligned register
// pair -> zero pack MOVs in the inner loop (R14 post-mortem: those MOVs
// were ~10 of 32 issue slots per pair).
// Per-lane fma.rn.f32x2 is IEEE-identical to select's fmaf chain, so
// slice minima bit-match the rescan.
// Ordering key: e = |g|^2 - 2*s.g  (== d2 - |s|^2, same order as ref d2).
__global__ __launch_bounds__(SMT)
void slice_min_kernel(const float* __restrict__ src,
                      const float* __restrict__ grid) {
    __shared__ ulonglong2 tileA[NPAIR];   // (xx = x0|x1, yy = y0|y1)
    __shared__ ulonglong2 tileB[NPAIR];   // (zz = z0|z1, ww = w0|w1)

    const int slice = blockIdx.y;
    const int base  = slice * SL;
    const int n     = min(SL, NGRID - base);      // 196 or 20
    const int npair = (n + 1) >> 1;

    if (threadIdx.x < npair) {
        const int p  = threadIdx.x;
        const int g0 = base + 2 * p;
        const int g1 = g0 + 1;
        float x0 = grid[g0 * 3 + 0] / 1000.0f;
        float y0 = grid[g0 * 3 + 1] / 1000.0f;
        float z0 = grid[g0 * 3 + 2] / 1000.0f;
        float w0 = __fadd_rn(__fadd_rn(__fmul_rn(x0, x0), __fmul_rn(y0, y0)),
                             __fmul_rn(z0, z0));
        float x1 = 1e30f, y1 = 1e30f, z1 = 1e30f, w1 = 1e30f;  // pad -> huge e
        if (2 * p + 1 < n) {
            x1 = grid[g1 * 3 + 0] / 1000.0f;
            y1 = grid[g1 * 3 + 1] / 1000.0f;
            z1 = grid[g1 * 3 + 2] / 1000.0f;
            w1 = __fadd_rn(__fadd_rn(__fmul_rn(x1, x1), __fmul_rn(y1, y1)),
                           __fmul_rn(z1, z1));
        }
        ulonglong2 a, b;
        a.x = pk2(x0, x1); a.y = pk2(y0, y1);
        b.x = pk2(z0, z1); b.y = pk2(w0, w1);
        tileA[p] = a;
        tileB[p] = b;
    }
    __syncthreads();

    const int s0 = blockIdx.x * (SMT * SPT) + threadIdx.x;

    unsigned long long mx2[SPT], my2[SPT], mz2[SPT];
#pragma unroll
    for (int k = 0; k < SPT; k++) {
        const int s = s0 + k * SMT;
        float mx = -2.0f * (src[s * 3 + 0] / 1000.0f);
        float my = -2.0f * (src[s * 3 + 1] / 1000.0f);
        float mz = -2.0f * (src[s * 3 + 2] / 1000.0f);
        mx2[k] = pk2(mx, mx);
        my2[k] = pk2(my, my);
        mz2[k] = pk2(mz, mz);
    }

    float accL[SPT], accH[SPT];
#pragma unroll
    for (int k = 0; k < SPT; k++) { accL[k] = FINF; accH[k] = FINF; }

#pragma unroll 7
    for (int p = 0; p < npair; p++) {
        const ulonglong2 A = tileA[p];   // A.x = xx, A.y = yy
        const ulonglong2 B = tileB[p];   // B.x = zz, B.y = ww
#pragma unroll
        for (int k = 0; k < SPT; k++) {
            unsigned long long e = fma2(mz2[k], B.x, B.y);
            e = fma2(my2[k], A.y, e);
            e = fma2(mx2[k], A.x, e);
            float lo, hi;
            upk2(e, lo, hi);
            accL[k] = fminf(accL[k], lo);
            accH[k] = fminf(accH[k], hi);
        }
    }

#pragma unroll
    for (int k = 0; k < SPT; k++) {
        const int s = s0 + k * SMT;
        g_sd[s * NSLICE + slice] = fminf(accL[k], accH[k]);
    }
}

// ============ kernel 2: exact top-5 per source (3 barriers) ============
// (R14-proven) block = one source, 256 threads.
__global__ __launch_bounds__(256)
void select_kernel(const float* __restrict__ src,
                   const float* __restrict__ grid) {
    const int s    = blockIdx.x;
    const int t    = threadIdx.x;
    const int lane = t & 31;
    const int wid  = t >> 5;

    __shared__ float swv[8 * KTOP];
    __shared__ int   swj[8 * KTOP];
    __shared__ int   csl[KTOP];

    // ---- stage A: per-warp top-5 of slice minima ----
    {
        float v = g_sd[s * NSLICE + t];
        int   j = t;
#pragma unroll
        for (int r = 0; r < KTOP; r++) {
            float bv = v; int bi = j;
#pragma unroll
            for (int off = 16; off > 0; off >>= 1) {
                float ov = __shfl_xor_sync(0xffffffffu, bv, off);
                int   oi = __shfl_xor_sync(0xffffffffu, bi, off);
                if (lexless(ov, oi, bv, bi)) { bv = ov; bi = oi; }
            }
            if (lane == 0) { swv[wid * KTOP + r] = bv; swj[wid * KTOP + r] = bi; }
            if (v == bv && j == bi) { v = FINF; j = IBIG; }  // ids unique
        }
    }
    __syncthreads();

    // ---- warp 0: merge 8 sorted 5-lists -> csl ----
    if (wid == 0) {
        float h0 = FINF, h1 = FINF, h2 = FINF, h3 = FINF, h4 = FINF;
        int   g0 = IBIG, g1 = IBIG, g2 = IBIG, g3 = IBIG, g4 = IBIG;
        if (lane < 8) {
            h0 = swv[lane * KTOP + 0]; g0 = swj[lane * KTOP + 0];
            h1 = swv[lane * KTOP + 1]; g1 = swj[lane * KTOP + 1];
            h2 = swv[lane * KTOP + 2]; g2 = swj[lane * KTOP + 2];
            h3 = swv[lane * KTOP + 3]; g3 = swj[lane * KTOP + 3];
            h4 = swv[lane * KTOP + 4]; g4 = swj[lane * KTOP + 4];
        }
#pragma unroll
        for (int r = 0; r < KTOP; r++) {
            float bv = h0; int bi = g0;
#pragma unroll
            for (int off = 16; off > 0; off >>= 1) {
                float ov = __shfl_xor_sync(0xffffffffu, bv, off);
                int   oi = __shfl_xor_sync(0xffffffffu, bi, off);
                if (lexless(ov, oi, bv, bi)) { bv = ov; bi = oi; }
            }
            if (lane == 0) csl[r] = bi;
            if (h0 == bv && g0 == bi) {
                h0 = h1; g0 = g1; h1 = h2; g1 = g2;
                h2 = h3; g2 = g3; h3 = h4; g3 = g4;
                h4 = FINF; g4 = IBIG;
            }
        }
    }
    __syncthreads();

    // ---- stage B/C: rescan <=980 candidates, lane sort-4, warp merge ----
    const float mx = -2.0f * (src[s * 3 + 0] / 1000.0f);
    const float my = -2.0f * (src[s * 3 + 1] / 1000.0f);
    const float mz = -2.0f * (src[s * 3 + 2] / 1000.0f);

    float cv[4];
    int   cg[4];
#pragma unroll
    for (int i = 0; i < 4; i++) {
        const int p = t + 256 * i;
        float e = FINF;
        int   gidx = IBIG;
        if (p < KTOP * SL) {
            const int k  = p / SL;
            const int jj = p - k * SL;
            const int gi = csl[k] * SL + jj;
            if (gi < NGRID) {
                float x = grid[gi * 3 + 0] / 1000.0f;
                float y = grid[gi * 3 + 1] / 1000.0f;
                float z = grid[gi * 3 + 2] / 1000.0f;
                float n2 = __fadd_rn(__fadd_rn(__fmul_rn(x, x),
                                               __fmul_rn(y, y)),
                                     __fmul_rn(z, z));
                e = fmaf(mx, x, fmaf(my, y, fmaf(mz, z, n2)));
                gidx = gi;
            }
        }
        cv[i] = e;
        cg[i] = gidx;
    }

    // branchless sort-4 ascending by (e, gidx)
#define CE(a, b) { bool sw = lexless(cv[b], cg[b], cv[a], cg[a]);            \
                   float tv = sw ? cv[b] : cv[a]; float uv = sw ? cv[a] : cv[b]; \
                   int   tg = sw ? cg[b] : cg[a]; int   ug = sw ? cg[a] : cg[b]; \
                   cv[a] = tv; cv[b] = uv; cg[a] = tg; cg[b] = ug; }
    CE(0, 1) CE(2, 3) CE(0, 2) CE(1, 3) CE(1, 2)
#undef CE

    // warp merge: top-5 over 32 sorted 4-lists
#pragma unroll
    for (int r = 0; r < KTOP; r++) {
        float bv = cv[0]; int bi = cg[0];
#pragma unroll
        for (int off = 16; off > 0; off >>= 1) {
            float ov = __shfl_xor_sync(0xffffffffu, bv, off);
            int   oi = __shfl_xor_sync(0xffffffffu, bi, off);
            if (lexless(ov, oi, bv, bi)) { bv = ov; bi = oi; }
        }
        if (lane == 0) { swv[wid * KTOP + r] = bv; swj[wid * KTOP + r] = bi; }
        if (cv[0] == bv && cg[0] == bi) {   // real ids unique; INF pads benign
            cv[0] = cv[1]; cg[0] = cg[1]; cv[1] = cv[2]; cg[1] = cg[2];
            cv[2] = cv[3]; cg[2] = cg[3]; cv[3] = FINF; cg[3] = IBIG;
        }
    }
    __syncthreads();

    // ---- warp 0: merge 8 sorted 5-lists -> g_topk ----
    if (wid == 0) {
        float h0 = FINF, h1 = FINF, h2 = FINF, h3 = FINF, h4 = FINF;
        int   g0 = IBIG, g1 = IBIG, g2 = IBIG, g3 = IBIG, g4 = IBIG;
        if (lane < 8) {
            h0 = swv[lane * KTOP + 0]; g0 = swj[lane * KTOP + 0];
            h1 = swv[lane * KTOP + 1]; g1 = swj[lane * KTOP + 1];
            h2 = swv[lane * KTOP + 2]; g2 = swj[lane * KTOP + 2];
            h3 = swv[lane * KTOP + 3]; g3 = swj[lane * KTOP + 3];
            h4 = swv[lane * KTOP + 4]; g4 = swj[lane * KTOP + 4];
        }
#pragma unroll
        for (int r = 0; r < KTOP; r++) {
            float bv = h0; int bi = g0;
#pragma unroll
            for (int off = 16; off > 0; off >>= 1) {
                float ov = __shfl_xor_sync(0xffffffffu, bv, off);
                int   oi = __shfl_xor_sync(0xffffffffu, bi, off);
                if (lexless(ov, oi, bv, bi)) { bv = ov; bi = oi; }
            }
            if (lane == 0) g_topk[s * KTOP + r] = bi;
            if (h0 == bv && g0 == bi) {
                h0 = h1; g0 = g1; h1 = h2; g1 = g2;
                h2 = h3; g2 = g3; h3 = h4; g3 = g4;
                h4 = FINF; g4 = IBIG;
            }
        }
    }
}

// ============ kernel 3: fused tail — 4 sources per block ============
// (R8-exact) 512 blocks x 512 threads.
__global__ __launch_bounds__(512)
void tail_kernel(const float* __restrict__ src,
                 const int*   __restrict__ ind,
                 const float* __restrict__ log_amp,
                 const int*   __restrict__ phase,
                 const float* __restrict__ locs,
                 const float* __restrict__ mag_coef,
                 const float* __restrict__ eps_coef,
                 const float* __restrict__ dep_coef,
                 const float* __restrict__ bias,
                 float*       __restrict__ out) {
    const int s0  = blockIdx.x * 4;
    const int tid = threadIdx.x;

    __shared__ float bsum[4][NLOCS];
    __shared__ int   tks[4 * KTOP];

    if (tid < 4 * KTOP) tks[tid] = g_topk[s0 * KTOP + tid];
    __syncthreads();

    const int ph = phase[0];

    // ---- stage 1: bias means for 4 sources ----
    for (int task = tid; task < 4 * NLOCS; task += 512) {
        const int ss = task / NLOCS;
        const int j  = task - ss * NLOCS;
        const int col = j * 2 + ph;
        float acc = __ldg(&bias[(size_t)tks[ss * KTOP + 0] * (NLOCS * 2) + col]);
        acc += __ldg(&bias[(size_t)tks[ss * KTOP + 1] * (NLOCS * 2) + col]);
        acc += __ldg(&bias[(size_t)tks[ss * KTOP + 2] * (NLOCS * 2) + col]);
        acc += __ldg(&bias[(size_t)tks[ss * KTOP + 3] * (NLOCS * 2) + col]);
        acc += __ldg(&bias[(size_t)tks[ss * KTOP + 4] * (NLOCS * 2) + col]);
        bsum[ss][j] = acc / 5.0f;
    }
    __syncthreads();

    // ---- stage 2: epilogue, 4 outputs per thread ----
    if (tid >= NLOCS) return;

    const float ec    = eps_coef[ph];
    const float dc    = dep_coef[ph];
    const float denom = fmaxf(mag_coef[ph], 1e-12f);

    const int li = ind[tid];
    const float lx = locs[li * 3 + 0];
    const float ly = locs[li * 3 + 1];
    const float lz = locs[li * 3 + 2];

#pragma unroll
    for (int ss = 0; ss < 4; ss++) {
        const int s = s0 + ss;
        const float sx = src[s * 3 + 0];
        const float sy = src[s * 3 + 1];
        const float sz = src[s * 3 + 2];

        const float dx = sx - lx;
        const float dy = sy - ly;
        const float d0  = fsqrt_approx(__fadd_rn(__fmul_rn(dx, dx),
                                                 __fmul_rn(dy, dy)));
        const float ld0 = __log10f(d0 + 1.0f);
        const float ldd = __log10f(fabsf(sz - lz) + 1.0f);

        const float b  = bsum[ss][li];
        const float la = log_amp[s * NLOCS + tid];
        out[s * NLOCS + tid] = (la - ec * ld0 - dc * ldd - b) / denom;
    }
}

// ---------------- launch ----------------
extern "C" void kernel_launch(void* const* d_in, const int* in_sizes, int n_in,
                              void* d_out, int out_size) {
    const float* src      = (const float*)d_in[0];
    const int*   ind      = (const int*)  d_in[1];
    const float* log_amp  = (const float*)d_in[2];
    const int*   phase    = (const int*)  d_in[3];
    const float* locs     = (const float*)d_in[4];
    const float* grid     = (const float*)d_in[5];
    const float* mag_coef = (const float*)d_in[6];
    const float* eps_coef = (const float*)d_in[7];
    const float* dep_coef = (const float*)d_in[8];
    const float* bias     = (const float*)d_in[9];
    float* out = (float*)d_out;

    dim3 g1(NSRC / (SMT * SPT), NSLICE);
    slice_min_kernel<<<g1, SMT>>>(src, grid);

    select_kernel<<<NSRC, 256>>>(src, grid);

    tail_kernel<<<NSRC / 4, 512>>>(src, ind, log_amp, phase, locs,
                                   mag_coef, eps_coef, dep_coef, bias, out);
}